// round 1
// baseline (speedup 1.0000x reference)
#include <cuda_runtime.h>

#define DD   256
#define NN   8192
#define EE   8191
#define ALPHA 0.2f

// ---------------- scratch (allocation-free: __device__ globals) ----------------
__device__ float g_w12[2 * DD];     // w1 = a[0:256]^T W, w2 = a[256:512]^T W
__device__ float g_p[NN];
__device__ float g_q[NN];
__device__ float g_coef[NN];
__device__ int   g_inv_dep[NN];
__device__ int   g_inv_gov[NN];

// ---------------- K1: w1[k] = sum_j a[j] W[j,k] ; w2[k] = sum_j a[D+j] W[j,k] ----
__global__ void k_w(const float* __restrict__ a, const float* __restrict__ W) {
    int half = blockIdx.x;          // 0 -> w1, 1 -> w2
    int k = threadIdx.x;
    const float* ah = a + half * DD;
    float acc = 0.f;
#pragma unroll 8
    for (int j = 0; j < DD; j++)
        acc += ah[j] * W[j * DD + k];
    g_w12[half * DD + k] = acc;
}

// ---------------- K2: p[i] = x[i].w1, q[i] = x[i].w2 (one warp per row) ---------
__global__ void k_pq(const float* __restrict__ x) {
    int row  = blockIdx.x * 8 + (threadIdx.x >> 5);
    int lane = threadIdx.x & 31;
    const float4* xr = (const float4*)(x + row * DD);
    const float4* w4 = (const float4*)g_w12;

    float4 xa = xr[lane * 2], xb = xr[lane * 2 + 1];
    float4 wa = w4[lane * 2], wb = w4[lane * 2 + 1];
    float4 va = w4[64 + lane * 2], vb = w4[64 + lane * 2 + 1];

    float p = xa.x * wa.x + xa.y * wa.y + xa.z * wa.z + xa.w * wa.w
            + xb.x * wb.x + xb.y * wb.y + xb.z * wb.z + xb.w * wb.w;
    float q = xa.x * va.x + xa.y * va.y + xa.z * va.z + xa.w * va.w
            + xb.x * vb.x + xb.y * vb.y + xb.z * vb.z + xb.w * vb.w;
#pragma unroll
    for (int o = 16; o; o >>= 1) {
        p += __shfl_xor_sync(0xFFFFFFFFu, p, o);
        q += __shfl_xor_sync(0xFFFFFFFFu, q, o);
    }
    if (lane == 0) { g_p[row] = p; g_q[row] = q; }
}

// ---------------- K3: reset inverse maps ---------------------------------------
__global__ void k_init() {
    int i = blockIdx.x * blockDim.x + threadIdx.x;
    if (i < NN) { g_inv_dep[i] = -1; g_inv_gov[i] = -1; }
}

// ---------------- K4: coef + scatter inverse maps -------------------------------
__global__ void k_scatter(const int* __restrict__ dep, const int* __restrict__ gov) {
    int e = blockIdx.x * blockDim.x + threadIdx.x;
    if (e < EE) {
        int d = dep[e], g = gov[e];
        float s = g_p[g] + g_q[d];
        g_coef[e]    = (s > 0.f) ? 1.f : (1.f / (float)NN);
        g_inv_dep[d] = e;     // dep unique -> no conflict
        g_inv_gov[g] = e;     // gov unique -> no conflict
    }
}

// ---------------- K5: fused gather + SGEMM (y @ W^T) + leaky relu ---------------
// y[r] = cA*x[srcA] + cB*x[srcB];  out[r][n] = lrelu( sum_k y[r][k] * W[n][k] )
__device__ __forceinline__ float lrelu(float v) { return v > 0.f ? v : ALPHA * v; }

__global__ __launch_bounds__(256, 1) void k_gemm(
    const float* __restrict__ x, const float* __restrict__ W,
    const int* __restrict__ dep, const int* __restrict__ gov,
    float* __restrict__ out)
{
    const int BM = 128, BN = 128;
    __shared__ float As[16][BM + 4];
    __shared__ float Bs[16][BN + 4];

    int tid = threadIdx.x;
    int m0 = blockIdx.y * BM;
    int n0 = blockIdx.x * BN;

    // global-load assignment: 512 float4 slots (128 rows x 4 quads), 2 per thread
    int r0 = tid >> 2;       // 0..63
    int q0 = tid & 3;        // quad within the 16-wide k tile
    int r1 = r0 + 64;

    // per-row gather parameters (fixed for the whole k loop)
    int sA0, sB0, sA1, sB1; float cA0, cB0, cA1, cB1;
    {
        int r  = m0 + r0;
        int ed = g_inv_dep[r], eg = g_inv_gov[r];
        sA0 = ed >= 0 ? gov[ed] : 0;  cA0 = ed >= 0 ? 1.f : 0.f;
        sB0 = eg >= 0 ? dep[eg] : 0;  cB0 = eg >= 0 ? g_coef[eg] : 0.f;
    }
    {
        int r  = m0 + r1;
        int ed = g_inv_dep[r], eg = g_inv_gov[r];
        sA1 = ed >= 0 ? gov[ed] : 0;  cA1 = ed >= 0 ? 1.f : 0.f;
        sB1 = eg >= 0 ? dep[eg] : 0;  cB1 = eg >= 0 ? g_coef[eg] : 0.f;
    }

    const float4* x4 = (const float4*)x;
    const float4* W4 = (const float4*)W;
    int wn0 = (n0 + r0) * 64 + q0;
    int wn1 = (n0 + r1) * 64 + q0;
    int ax0 = sA0 * 64 + q0, bx0 = sB0 * 64 + q0;
    int ax1 = sA1 * 64 + q0, bx1 = sB1 * 64 + q0;

    float4 pA0g, pA0b, pA1g, pA1b, pB0, pB1;

    // prologue: load tile kt=0
    {
        pA0g = x4[ax0]; pA0b = x4[bx0];
        pA1g = x4[ax1]; pA1b = x4[bx1];
        pB0  = W4[wn0]; pB1  = W4[wn1];
    }
    {
        int kl = q0 * 4;
        As[kl + 0][r0] = cA0 * pA0g.x + cB0 * pA0b.x;
        As[kl + 1][r0] = cA0 * pA0g.y + cB0 * pA0b.y;
        As[kl + 2][r0] = cA0 * pA0g.z + cB0 * pA0b.z;
        As[kl + 3][r0] = cA0 * pA0g.w + cB0 * pA0b.w;
        As[kl + 0][r1] = cA1 * pA1g.x + cB1 * pA1b.x;
        As[kl + 1][r1] = cA1 * pA1g.y + cB1 * pA1b.y;
        As[kl + 2][r1] = cA1 * pA1g.z + cB1 * pA1b.z;
        As[kl + 3][r1] = cA1 * pA1g.w + cB1 * pA1b.w;
        Bs[kl + 0][r0] = pB0.x; Bs[kl + 1][r0] = pB0.y;
        Bs[kl + 2][r0] = pB0.z; Bs[kl + 3][r0] = pB0.w;
        Bs[kl + 0][r1] = pB1.x; Bs[kl + 1][r1] = pB1.y;
        Bs[kl + 2][r1] = pB1.z; Bs[kl + 3][r1] = pB1.w;
    }
    __syncthreads();

    float acc[8][8];
#pragma unroll
    for (int i = 0; i < 8; i++)
#pragma unroll
        for (int j = 0; j < 8; j++) acc[i][j] = 0.f;

    int tx = tid & 15, ty = tid >> 4;   // 16x16 thread grid, 8x8 tile each

#pragma unroll 1
    for (int kt = 16; kt <= DD; kt += 16) {
        bool more = (kt < DD);
        if (more) {                       // register prefetch of next tile
            int kq = kt >> 2;
            pA0g = x4[ax0 + kq]; pA0b = x4[bx0 + kq];
            pA1g = x4[ax1 + kq]; pA1b = x4[bx1 + kq];
            pB0  = W4[wn0 + kq]; pB1  = W4[wn1 + kq];
        }
#pragma unroll
        for (int kk = 0; kk < 16; kk++) {
            float4 a0 = *(const float4*)&As[kk][ty * 8];
            float4 a1 = *(const float4*)&As[kk][ty * 8 + 4];
            float4 b0 = *(const float4*)&Bs[kk][tx * 8];
            float4 b1 = *(const float4*)&Bs[kk][tx * 8 + 4];
            float av[8] = {a0.x, a0.y, a0.z, a0.w, a1.x, a1.y, a1.z, a1.w};
            float bv[8] = {b0.x, b0.y, b0.z, b0.w, b1.x, b1.y, b1.z, b1.w};
#pragma unroll
            for (int i = 0; i < 8; i++)
#pragma unroll
                for (int j = 0; j < 8; j++)
                    acc[i][j] += av[i] * bv[j];
        }
        __syncthreads();
        if (more) {
            int kl = q0 * 4;
            As[kl + 0][r0] = cA0 * pA0g.x + cB0 * pA0b.x;
            As[kl + 1][r0] = cA0 * pA0g.y + cB0 * pA0b.y;
            As[kl + 2][r0] = cA0 * pA0g.z + cB0 * pA0b.z;
            As[kl + 3][r0] = cA0 * pA0g.w + cB0 * pA0b.w;
            As[kl + 0][r1] = cA1 * pA1g.x + cB1 * pA1b.x;
            As[kl + 1][r1] = cA1 * pA1g.y + cB1 * pA1b.y;
            As[kl + 2][r1] = cA1 * pA1g.z + cB1 * pA1b.z;
            As[kl + 3][r1] = cA1 * pA1g.w + cB1 * pA1b.w;
            Bs[kl + 0][r0] = pB0.x; Bs[kl + 1][r0] = pB0.y;
            Bs[kl + 2][r0] = pB0.z; Bs[kl + 3][r0] = pB0.w;
            Bs[kl + 0][r1] = pB1.x; Bs[kl + 1][r1] = pB1.y;
            Bs[kl + 2][r1] = pB1.z; Bs[kl + 3][r1] = pB1.w;
            __syncthreads();
        }
    }

    // epilogue: leaky relu, vectorized stores
#pragma unroll
    for (int i = 0; i < 8; i++) {
        int m = m0 + ty * 8 + i;
        float4 o0, o1;
        o0.x = lrelu(acc[i][0]); o0.y = lrelu(acc[i][1]);
        o0.z = lrelu(acc[i][2]); o0.w = lrelu(acc[i][3]);
        o1.x = lrelu(acc[i][4]); o1.y = lrelu(acc[i][5]);
        o1.z = lrelu(acc[i][6]); o1.w = lrelu(acc[i][7]);
        *(float4*)&out[m * DD + n0 + tx * 8]     = o0;
        *(float4*)&out[m * DD + n0 + tx * 8 + 4] = o1;
    }
}

// ---------------- launch ---------------------------------------------------------
extern "C" void kernel_launch(void* const* d_in, const int* in_sizes, int n_in,
                              void* d_out, int out_size) {
    const float* x   = (const float*)d_in[0];
    const float* W   = (const float*)d_in[1];
    const float* a   = (const float*)d_in[2];
    const int*   dep = (const int*)d_in[3];
    const int*   gov = (const int*)d_in[4];
    float* out = (float*)d_out;

    k_w<<<2, 256>>>(a, W);
    k_pq<<<NN / 8, 256>>>(x);
    k_init<<<NN / 256, 256>>>();
    k_scatter<<<(EE + 255) / 256, 256>>>(dep, gov);
    k_gemm<<<dim3(2, 64), 256>>>(x, W, dep, gov, out);
}

// round 2
// speedup vs baseline: 1.4806x; 1.4806x over previous
#include <cuda_runtime.h>

#define DD   256
#define NN   8192
#define EE   8191
#define ALPHA 0.2f

// ---------------- scratch (allocation-free: __device__ globals) ----------------
__device__ float g_w12[2 * DD];     // w1 = a[0:256]^T W, w2 = a[256:512]^T W
__device__ float g_p[NN];
__device__ float g_q[NN];
// per-output-row gather tables: out_row r = lrelu((cA*x[sA] + cB*x[sB]) @ W^T)
__device__ float g_cA[NN];
__device__ float g_cB[NN];
__device__ int   g_sA[NN];
__device__ int   g_sB[NN];

// ---------------- K1: fused init + w vectors ------------------------------------
__global__ void k_prep(const float* __restrict__ a, const float* __restrict__ W) {
    int b = blockIdx.x, t = threadIdx.x;
    if (b < 32) {
        int i = b * 256 + t;
        g_cA[i] = 0.f; g_cB[i] = 0.f; g_sA[i] = 0; g_sB[i] = 0;
    } else {
        int half = b - 32;                 // 0 -> w1, 1 -> w2
        const float* ah = a + half * DD;
        float acc = 0.f;
#pragma unroll 8
        for (int j = 0; j < DD; j++)
            acc += ah[j] * W[j * DD + t];
        g_w12[half * DD + t] = acc;
    }
}

// ---------------- K2: p[i] = x[i].w1, q[i] = x[i].w2 (one warp per row) ---------
__global__ void k_pq(const float* __restrict__ x) {
    int row  = blockIdx.x * 8 + (threadIdx.x >> 5);
    int lane = threadIdx.x & 31;
    const float4* xr = (const float4*)(x + row * DD);
    const float4* w4 = (const float4*)g_w12;

    float4 xa = xr[lane * 2], xb = xr[lane * 2 + 1];
    float4 wa = w4[lane * 2], wb = w4[lane * 2 + 1];
    float4 va = w4[64 + lane * 2], vb = w4[64 + lane * 2 + 1];

    float p = xa.x * wa.x + xa.y * wa.y + xa.z * wa.z + xa.w * wa.w
            + xb.x * wb.x + xb.y * wb.y + xb.z * wb.z + xb.w * wb.w;
    float q = xa.x * va.x + xa.y * va.y + xa.z * va.z + xa.w * va.w
            + xb.x * vb.x + xb.y * vb.y + xb.z * vb.z + xb.w * vb.w;
#pragma unroll
    for (int o = 16; o; o >>= 1) {
        p += __shfl_xor_sync(0xFFFFFFFFu, p, o);
        q += __shfl_xor_sync(0xFFFFFFFFu, q, o);
    }
    if (lane == 0) { g_p[row] = p; g_q[row] = q; }
}

// ---------------- K3: coef + per-row gather tables -------------------------------
__global__ void k_scatter(const int* __restrict__ dep, const int* __restrict__ gov) {
    int e = blockIdx.x * blockDim.x + threadIdx.x;
    if (e < EE) {
        int d = dep[e], g = gov[e];
        float s = g_p[g] + g_q[d];
        float coef = (s > 0.f) ? 1.f : (1.f / (float)NN);
        // h[dep] = Hx[gov]  -> row d gathers x[g] with weight 1
        g_cA[d] = 1.f;  g_sA[d] = g;
        // h[gov] += coef * Hx[dep] -> row g gathers x[d] with weight coef
        g_cB[g] = coef; g_sB[g] = d;
    }
}

// ---------------- K4: fused gather + tf32 tensor-core GEMM + leaky relu ---------
__device__ __forceinline__ unsigned f2tf(float f) {
    unsigned r; asm("cvt.rna.tf32.f32 %0, %1;" : "=r"(r) : "f"(f)); return r;
}
__device__ __forceinline__ float tfbits(float f) { return __uint_as_float(f2tf(f)); }
__device__ __forceinline__ float lrelu(float v) { return v > 0.f ? v : ALPHA * v; }
__device__ __forceinline__ unsigned su32(const void* p) {
    return (unsigned)__cvta_generic_to_shared(p);
}

// BM=128, BN=128, BK=32; 8 warps in 2(m) x 4(n); warp tile 64x32 (m16n8k8 frags)
__global__ __launch_bounds__(256, 1) void k_gemm(
    const float* __restrict__ x, const float* __restrict__ W,
    float* __restrict__ out)
{
    __shared__ float As[128 * 36];   // [row][36] padded: ldmatrix conflict-free
    __shared__ float Bs[128 * 36];

    int tid = threadIdx.x;
    int m0 = blockIdx.y * 128;
    int n0 = blockIdx.x * 128;

    // ---- global-load assignment: 2 threads per row, 4 float4 each (BK=32) ----
    int lrow = tid >> 1;          // 0..127
    int h    = tid & 1;           // which half of the 32-float k-slab
    int row  = m0 + lrow;
    float cA = g_cA[row], cB = g_cB[row];
    int   sA = g_sA[row], sB = g_sB[row];

    const float4* x4 = (const float4*)x;
    const float4* W4 = (const float4*)W;
    int aOff = sA * 64 + h * 4;
    int bOff = sB * 64 + h * 4;
    int wOff = (n0 + lrow) * 64 + h * 4;
    int sB0  = lrow * 36 + h * 16;   // smem store base (floats)

    float4 rg[4], rb[4], rw[4];
#pragma unroll
    for (int j = 0; j < 4; j++) { rg[j] = x4[aOff + j]; rb[j] = x4[bOff + j]; rw[j] = W4[wOff + j]; }

    // ---- fragment addressing ----
    int wid  = tid >> 5, lane = tid & 31;
    int wm   = (wid & 1) * 64;
    int wn   = (wid >> 1) * 32;
    int aRow = wm + (lane & 7) + ((lane & 8) ? 8 : 0);
    int aCol = (lane & 16) ? 4 : 0;
    unsigned aBase = su32(&As[aRow * 36 + aCol]);
    int bRow = wn + (lane & 7);
    int bCol = (lane & 8) ? 4 : 0;
    unsigned bBase = su32(&Bs[bRow * 36 + bCol]);

    float acc[4][4][4];
#pragma unroll
    for (int i = 0; i < 4; i++)
#pragma unroll
        for (int j = 0; j < 4; j++)
#pragma unroll
            for (int v = 0; v < 4; v++) acc[i][j][v] = 0.f;

#pragma unroll 1
    for (int kt = 0; kt < 8; kt++) {
        // store staged tile (combine A gather, round both operands to tf32 once)
#pragma unroll
        for (int j = 0; j < 4; j++) {
            int o = sB0 + j * 4;
            As[o + 0] = tfbits(cA * rg[j].x + cB * rb[j].x);
            As[o + 1] = tfbits(cA * rg[j].y + cB * rb[j].y);
            As[o + 2] = tfbits(cA * rg[j].z + cB * rb[j].z);
            As[o + 3] = tfbits(cA * rg[j].w + cB * rb[j].w);
            Bs[o + 0] = tfbits(rw[j].x);
            Bs[o + 1] = tfbits(rw[j].y);
            Bs[o + 2] = tfbits(rw[j].z);
            Bs[o + 3] = tfbits(rw[j].w);
        }
        __syncthreads();
        if (kt < 7) {                    // prefetch next k-slab into registers
            int kq = (kt + 1) * 8;
#pragma unroll
            for (int j = 0; j < 4; j++) {
                rg[j] = x4[aOff + kq + j];
                rb[j] = x4[bOff + kq + j];
                rw[j] = W4[wOff + kq + j];
            }
        }
#pragma unroll
        for (int ks = 0; ks < 4; ks++) {
            int k = ks * 8;
            unsigned a[4][4], bf[4][2];
#pragma unroll
            for (int mf = 0; mf < 4; mf++)
                asm volatile("ldmatrix.sync.aligned.m8n8.x4.shared.b16 {%0,%1,%2,%3}, [%4];"
                    : "=r"(a[mf][0]), "=r"(a[mf][1]), "=r"(a[mf][2]), "=r"(a[mf][3])
                    : "r"(aBase + (unsigned)((mf * 576 + k) * 4)));
#pragma unroll
            for (int nf = 0; nf < 4; nf++)
                asm volatile("ldmatrix.sync.aligned.m8n8.x2.shared.b16 {%0,%1}, [%2];"
                    : "=r"(bf[nf][0]), "=r"(bf[nf][1])
                    : "r"(bBase + (unsigned)((nf * 288 + k) * 4)));
#pragma unroll
            for (int mf = 0; mf < 4; mf++)
#pragma unroll
                for (int nf = 0; nf < 4; nf++)
                    asm volatile(
                        "mma.sync.aligned.m16n8k8.row.col.f32.tf32.tf32.f32 "
                        "{%0,%1,%2,%3}, {%4,%5,%6,%7}, {%8,%9}, {%0,%1,%2,%3};"
                        : "+f"(acc[mf][nf][0]), "+f"(acc[mf][nf][1]),
                          "+f"(acc[mf][nf][2]), "+f"(acc[mf][nf][3])
                        : "r"(a[mf][0]), "r"(a[mf][1]), "r"(a[mf][2]), "r"(a[mf][3]),
                          "r"(bf[nf][0]), "r"(bf[nf][1]));
        }
        __syncthreads();
    }

    // ---- epilogue: leaky relu, float2 stores ----
    int er = m0 + wm + (lane >> 2);
    int ec = n0 + wn + (lane & 3) * 2;
#pragma unroll
    for (int mf = 0; mf < 4; mf++) {
#pragma unroll
        for (int nf = 0; nf < 4; nf++) {
            float2 v0, v1;
            v0.x = lrelu(acc[mf][nf][0]); v0.y = lrelu(acc[mf][nf][1]);
            v1.x = lrelu(acc[mf][nf][2]); v1.y = lrelu(acc[mf][nf][3]);
            *(float2*)&out[(er + mf * 16) * DD + ec + nf * 8]     = v0;
            *(float2*)&out[(er + mf * 16 + 8) * DD + ec + nf * 8] = v1;
        }
    }
}

// ---------------- launch ---------------------------------------------------------
extern "C" void kernel_launch(void* const* d_in, const int* in_sizes, int n_in,
                              void* d_out, int out_size) {
    const float* x   = (const float*)d_in[0];
    const float* W   = (const float*)d_in[1];
    const float* a   = (const float*)d_in[2];
    const int*   dep = (const int*)d_in[3];
    const int*   gov = (const int*)d_in[4];
    float* out = (float*)d_out;

    k_prep<<<34, 256>>>(a, W);
    k_pq<<<NN / 8, 256>>>(x);
    k_scatter<<<32, 256>>>(dep, gov);
    k_gemm<<<dim3(2, 64), 256>>>(x, W, out);
}